// round 15
// baseline (speedup 1.0000x reference)
#include <cuda_runtime.h>
#include <cstdint>

#define BN_EPS_F 1e-3f

__device__ __align__(16) float g_w1f[256*128];
__device__ float g_b1[128];
__device__ __align__(16) unsigned char g_w2q[9*128*128]; // [tap][co][ci] s8
__device__ float g_b2[128];
__device__ __align__(16) unsigned char g_w3q[512*128];   // [co][ci] s8
__device__ float g_b3[512];
__device__ float g_inv[2];
// [0]=c1, [1]=c2a, [2]=c2b, [3]=c3a, [4]=c3b, [5..36]=done1[n], [37..68]=done2[n]
__device__ int   g_sync[69];
__device__ unsigned g_wmax[3];
__device__ __align__(16) unsigned g_act1[100352*32];
__device__ __align__(16) unsigned g_act2[100352*32];

__device__ __forceinline__ uint32_t smem_u32(const void* p){
    uint32_t a;
    asm("{ .reg .u64 t; cvta.to.shared.u64 t, %1; cvt.u32.u64 %0, t; }" : "=r"(a) : "l"(p));
    return a;
}
#define SWZ(o) ((o) ^ (((o) >> 3) & 0x70))

__device__ __forceinline__ void ldsm4(unsigned* r, uint32_t addr){
    asm volatile("ldmatrix.sync.aligned.m8n8.x4.shared.b16 {%0,%1,%2,%3}, [%4];"
        : "=r"(r[0]), "=r"(r[1]), "=r"(r[2]), "=r"(r[3]) : "r"(addr));
}
__device__ __forceinline__ void mma_u8s8(int* d, const unsigned* a, const unsigned* b){
    asm volatile("mma.sync.aligned.m16n8k32.row.col.s32.u8.s8.s32 "
        "{%0,%1,%2,%3}, {%4,%5,%6,%7}, {%8,%9}, {%0,%1,%2,%3};"
        : "+r"(d[0]), "+r"(d[1]), "+r"(d[2]), "+r"(d[3])
        : "r"(a[0]), "r"(a[1]), "r"(a[2]), "r"(a[3]), "r"(b[0]), "r"(b[1]));
}
__device__ __forceinline__ void mma_s8u8(int* d, const unsigned* a, const unsigned* b){
    asm volatile("mma.sync.aligned.m16n8k32.row.col.s32.s8.u8.s32 "
        "{%0,%1,%2,%3}, {%4,%5,%6,%7}, {%8,%9}, {%0,%1,%2,%3};"
        : "+r"(d[0]), "+r"(d[1]), "+r"(d[2]), "+r"(d[3])
        : "r"(a[0]), "r"(a[1]), "r"(a[2]), "r"(a[3]), "r"(b[0]), "r"(b[1]));
}
#define CPA(dst, src, sz) asm volatile("cp.async.cg.shared.global [%0], [%1], 16, %2;" :: "r"(dst), "l"(src), "r"(sz) : "memory")
#define CPC()  asm volatile("cp.async.commit_group;" ::: "memory")
#define CPW(n) asm volatile("cp.async.wait_group %0;" :: "n"(n) : "memory")

// ---------------- prep pass 1 (unchanged) ----------------
__global__ __launch_bounds__(512) void prep_max(
    const float* __restrict__ w1, const float* __restrict__ g1, const float* __restrict__ v1,
    const float* __restrict__ w2, const float* __restrict__ g2, const float* __restrict__ v2,
    const float* __restrict__ w3, const float* __restrict__ g3, const float* __restrict__ v3)
{
    __shared__ float sc[512]; __shared__ float red[512];
    int tid = threadIdx.x;
    int grp = blockIdx.x >> 5, sub = blockIdx.x & 31;
    float lmax = 0.f;
    if (grp == 0) {
        if (tid < 128) sc[tid] = __fdiv_rn(g1[tid], __fsqrt_rn(__fadd_rn(v1[tid], BN_EPS_F)));
        __syncthreads();
        int base = sub * 1024;
        for (int i = base + tid; i < base + 1024; i += 512)
            lmax = fmaxf(lmax, fabsf(__fmul_rn(w1[i], sc[i >> 8])));
    } else if (grp == 1) {
        if (tid < 128) sc[tid] = __fdiv_rn(g2[tid], __fsqrt_rn(__fadd_rn(v2[tid], BN_EPS_F)));
        __syncthreads();
        int base = sub * 4608;
        for (int i = base + tid; i < base + 4608; i += 512)
            lmax = fmaxf(lmax, fabsf(__fmul_rn(w2[i], sc[i / 1152])));
    } else {
        sc[tid] = __fdiv_rn(g3[tid], __fsqrt_rn(__fadd_rn(v3[tid], BN_EPS_F)));
        __syncthreads();
        int base = sub * 2048;
        for (int i = base + tid; i < base + 2048; i += 512)
            lmax = fmaxf(lmax, fabsf(__fmul_rn(w3[i], sc[i >> 7])));
    }
    red[tid] = lmax; __syncthreads();
    for (int s = 256; s > 0; s >>= 1) { if (tid < s) red[tid] = fmaxf(red[tid], red[tid+s]); __syncthreads(); }
    if (tid == 0) atomicMax(&g_wmax[grp], __float_as_uint(red[0]));
}

// ---------------- prep pass 2 (unchanged) ----------------
__global__ __launch_bounds__(512) void prep_quant(
    const float* __restrict__ w1, const float* __restrict__ b1,
    const float* __restrict__ g1, const float* __restrict__ be1,
    const float* __restrict__ m1, const float* __restrict__ v1,
    const float* __restrict__ w2, const float* __restrict__ b2,
    const float* __restrict__ g2, const float* __restrict__ be2,
    const float* __restrict__ m2, const float* __restrict__ v2,
    const float* __restrict__ w3, const float* __restrict__ b3,
    const float* __restrict__ g3, const float* __restrict__ be3,
    const float* __restrict__ m3, const float* __restrict__ v3)
{
    __shared__ float sc[512]; __shared__ float red[512];
    int tid = threadIdx.x;
    int grp = blockIdx.x >> 5, sub = blockIdx.x & 31;
    if (grp == 0) {
        if (tid < 128) sc[tid] = __fdiv_rn(g1[tid], __fsqrt_rn(__fadd_rn(v1[tid], BN_EPS_F)));
        __syncthreads();
        float sw = __fdiv_rn(127.f, fmaxf(__uint_as_float(g_wmax[0]), 1e-8f));
        int base = sub * 1024;
        for (int i = base + tid; i < base + 1024; i += 512) {
            float wf = __fmul_rn(w1[i], sc[i >> 8]);
            g_w1f[(i & 255) * 128 + (i >> 8)] = __fdiv_rn(rintf(__fmul_rn(wf, sw)), sw);
        }
        if (sub == 0) {
            float bf = 0.f;
            if (tid < 128) bf = __fadd_rn(__fmul_rn(__fsub_rn(b1[tid], m1[tid]), sc[tid]), be1[tid]);
            red[tid] = fabsf(bf); __syncthreads();
            for (int s = 256; s > 0; s >>= 1) { if (tid < s) red[tid] = fmaxf(red[tid], red[tid+s]); __syncthreads(); }
            float sb = __fdiv_rn(32767.f, fmaxf(red[0], 1e-8f));
            if (tid < 128) g_b1[tid] = __fdiv_rn(rintf(__fmul_rn(bf, sb)), sb);
        }
    } else if (grp == 1) {
        if (tid < 128) sc[tid] = __fdiv_rn(g2[tid], __fsqrt_rn(__fadd_rn(v2[tid], BN_EPS_F)));
        __syncthreads();
        float sw = __fdiv_rn(127.f, fmaxf(__uint_as_float(g_wmax[1]), 1e-8f));
        int base = sub * 4608;
        for (int i = base + tid; i < base + 4608; i += 512) {
            int o = i / 1152, rem = i - o * 1152, ci = rem / 9, t = rem - ci * 9;
            int q = (int)rintf(__fmul_rn(__fmul_rn(w2[i], sc[o]), sw));
            ((signed char*)g_w2q)[(t * 128 + o) * 128 + ci] = (signed char)q;
        }
        if (sub == 0) {
            float bf = 0.f;
            if (tid < 128) bf = __fadd_rn(__fmul_rn(__fsub_rn(b2[tid], m2[tid]), sc[tid]), be2[tid]);
            red[tid] = fabsf(bf); __syncthreads();
            for (int s = 256; s > 0; s >>= 1) { if (tid < s) red[tid] = fmaxf(red[tid], red[tid+s]); __syncthreads(); }
            float sb = __fdiv_rn(32767.f, fmaxf(red[0], 1e-8f));
            if (tid < 128) g_b2[tid] = __fdiv_rn(rintf(__fmul_rn(bf, sb)), sb);
            if (tid == 0)  g_inv[0] = __fdiv_rn(1.f, __fmul_rn(sw, 25.5f));
        }
    } else {
        sc[tid] = __fdiv_rn(g3[tid], __fsqrt_rn(__fadd_rn(v3[tid], BN_EPS_F)));
        __syncthreads();
        float sw = __fdiv_rn(127.f, fmaxf(__uint_as_float(g_wmax[2]), 1e-8f));
        int base = sub * 2048;
        for (int i = base + tid; i < base + 2048; i += 512)
            ((signed char*)g_w3q)[i] = (signed char)(int)rintf(__fmul_rn(__fmul_rn(w3[i], sc[i >> 7]), sw));
        if (sub == 0) {
            float bf = __fadd_rn(__fmul_rn(__fsub_rn(b3[tid], m3[tid]), sc[tid]), be3[tid]);
            red[tid] = fabsf(bf); __syncthreads();
            for (int s = 256; s > 0; s >>= 1) { if (tid < s) red[tid] = fmaxf(red[tid], red[tid+s]); __syncthreads(); }
            float sb = __fdiv_rn(32767.f, fmaxf(red[0], 1e-8f));
            g_b3[tid] = __fdiv_rn(rintf(__fmul_rn(bf, sb)), sb);
            if (tid == 0) g_inv[1] = __fdiv_rn(1.f, __fmul_rn(sw, 25.5f));
        }
    }
}

// ---------------- fused persistent kernel, 256 threads, 2 CTAs/SM, co-half split ----------------
__global__ __launch_bounds__(256, 2) void conv_fused(const float* __restrict__ x,
                                                     float* __restrict__ out)
{
    extern __shared__ char smem[];
    __shared__ int s_next;
    uint32_t sb = smem_u32(smem);
    int tid = threadIdx.x, wid = tid >> 5, lane = tid & 31;
    int parity = blockIdx.x & 1;

    float inv2 = g_inv[0], inv3 = g_inv[1];

    if (tid == 0) s_next = atomicAdd(&g_sync[0], 1);
    __syncthreads();
    int t = s_next;

    // ================= phase 1: conv1 fp32, 128px x 128co (unchanged) =================
    {
        float* Asb = (float*)smem;
        float* Wsb = (float*)(smem + 16384);
        int tr = tid >> 4, tc = tid & 15;
        int co0 = tr * 8;
        int pxa = tc * 4, pxb = tc * 4 + 64;
        int lr = tid >> 4;
        int lc1 = (tid & 15) * 4, lc2 = lc1 + 64;

        while (t < 800) {
            int n = t / 25, p0 = (t - n * 25) * 128;
            const float* xn = x + ((size_t)n * 256) * 3136;
            int pc1 = min(p0 + lc1, 3132), pc2 = min(p0 + lc2, 3132);

            float acc[8][8];
#pragma unroll
            for (int j = 0; j < 8; j++)
#pragma unroll
                for (int q = 0; q < 8; q++) acc[j][q] = 0.f;

            float4 a1 = *(const float4*)(xn + (size_t)lr * 3136 + pc1);
            float4 a2 = *(const float4*)(xn + (size_t)lr * 3136 + pc2);
            float4 w1 = *(const float4*)(g_w1f + lr * 128 + lc1);
            float4 w2 = *(const float4*)(g_w1f + lr * 128 + lc2);
            *(float4*)(Asb + lr * 128 + lc1) = a1;
            *(float4*)(Asb + lr * 128 + lc2) = a2;
            *(float4*)(Wsb + lr * 128 + lc1) = w1;
            *(float4*)(Wsb + lr * 128 + lc2) = w2;
            __syncthreads();

            for (int p = 0; p < 16; p++) {
                int cu = (p & 1) * 2048;
                if (p < 15) {
                    int kr = (p + 1) * 16 + lr;
                    a1 = *(const float4*)(xn + (size_t)kr * 3136 + pc1);
                    a2 = *(const float4*)(xn + (size_t)kr * 3136 + pc2);
                    w1 = *(const float4*)(g_w1f + kr * 128 + lc1);
                    w2 = *(const float4*)(g_w1f + kr * 128 + lc2);
                }
#pragma unroll
                for (int k = 0; k < 16; k++) {
                    float4 av0 = *(const float4*)(Asb + cu + k * 128 + pxa);
                    float4 av1 = *(const float4*)(Asb + cu + k * 128 + pxb);
                    float4 wv0 = *(const float4*)(Wsb + cu + k * 128 + co0);
                    float4 wv1 = *(const float4*)(Wsb + cu + k * 128 + co0 + 4);
                    float wreg[8] = {wv0.x, wv0.y, wv0.z, wv0.w, wv1.x, wv1.y, wv1.z, wv1.w};
                    float areg[8] = {av0.x, av0.y, av0.z, av0.w, av1.x, av1.y, av1.z, av1.w};
#pragma unroll
                    for (int j = 0; j < 8; j++)
#pragma unroll
                        for (int q = 0; q < 8; q++)
                            acc[j][q] += wreg[j] * areg[q];
                }
                if (p < 15) {
                    int nx = ((p + 1) & 1) * 2048;
                    *(float4*)(Asb + nx + lr * 128 + lc1) = a1;
                    *(float4*)(Asb + nx + lr * 128 + lc2) = a2;
                    *(float4*)(Wsb + nx + lr * 128 + lc1) = w1;
                    *(float4*)(Wsb + nx + lr * 128 + lc2) = w2;
                    __syncthreads();
                }
            }

            float bias[8];
#pragma unroll
            for (int j = 0; j < 8; j++) bias[j] = g_b1[co0 + j];
#pragma unroll
            for (int q = 0; q < 8; q++) {
                int p = p0 + (q < 4 ? (pxa + q) : (pxb + q - 4));
                if (p >= 3136) continue;
                unsigned b0 = 0, b1v = 0;
#pragma unroll
                for (int j = 0; j < 8; j++) {
                    float vv = acc[j][q] + bias[j];
                    vv = fminf(fmaxf(vv, 0.f), 10.f);
                    unsigned a = (unsigned)(int)rintf(vv * 25.5f);
                    if (j < 4) b0 |= a << (8 * j); else b1v |= a << (8 * (j - 4));
                }
                *(uint2*)&g_act1[((unsigned)(n * 3136 + p)) * 32 + tr * 2] = make_uint2(b0, b1v);
            }
            __threadfence();
            __syncthreads();
            if (tid == 0) { atomicAdd(&g_sync[5 + n], 1); s_next = atomicAdd(&g_sync[0], 1); }
            __syncthreads();
            t = s_next;
        }
    }

    // ================= phase 2: conv2 int8 mma, W streamed per tap, halo double-buffered =================
    // smem: WT0=0 (8K), WT1=8192 (8K), H0=16384 (23040), H1=39424 (23040), FB=62464
    const uint32_t WT0 = 0, WT1 = 8192, H0 = 16384, H1 = 39424, FBo = 62464;
    __syncthreads();
    if (tid < 64) ((float*)(smem + FBo))[tid] = g_b2[parity * 64 + tid];

    int wrb = (wid & 3) * 32, wcb = (wid >> 2) * 32;
    int sub = lane >> 3, r8 = lane & 7;
    int row8 = (sub & 1) * 8, kh = (sub >> 1) * 16;
    int rowb = (sub >> 1) * 8, khb = (sub & 1) * 16;

    int yym[2], xxm[2];
#pragma unroll
    for (int mt = 0; mt < 2; mt++) {
        int px = wrb + mt * 16 + row8 + r8;
        yym[mt] = px >> 4; xxm[mt] = px & 15;
    }
    uint32_t wof[2]; int wxx[2];
#pragma unroll
    for (int bt = 0; bt < 2; bt++) {
        int co = wcb + bt * 16 + rowb + r8;
        wof[bt] = co * 128;
        wxx[bt] = (co & 7) * 16;
    }

#define WTAP_LOAD(BASE, TAP) do { \
    for (int u = tid; u < 512; u += 256) { \
        int row = u >> 3, c16 = u & 7; \
        CPA((BASE) + SWZ(row * 128 + c16 * 16), \
            (const void*)(g_w2q + ((size_t)((TAP) * 128 + parity * 64 + row)) * 128 + c16 * 16), 16u); \
    } } while (0)

#define HALO_LOAD(BASE, N_, Y0_, X0_) do { \
    for (int u = tid; u < 1440; u += 256) { \
        int hrow = u >> 3, c16 = u & 7; \
        int iy = hrow / 18, ix = hrow - iy * 18; \
        int gy = (Y0_) + iy - 1, gx = (X0_) + ix - 1; \
        bool ok = (gy >= 0 && gy < 56 && gx >= 0 && gx < 56); \
        const void* src = ok ? (const void*)&g_act1[((unsigned)((N_) * 3136 + gy * 56 + gx)) * 32 + c16 * 4] \
                             : (const void*)g_act1; \
        CPA((BASE) + SWZ(hrow * 128 + c16 * 16), src, ok ? 16u : 0u); \
    } } while (0)

    {
        if (tid == 0) s_next = atomicAdd(&g_sync[1 + parity], 1);
        __syncthreads();
        int t2 = s_next;
        int hsel = 0, wsel = 0;

        if (t2 < 896) {
            int n = t2 / 28, r = t2 - n * 28;
            if (tid == 0) { while (((volatile int*)g_sync)[5 + n] < 25) {} }
            __syncthreads(); __threadfence();
            int y0 = (r >> 2) * 8, tx = r & 3;
            int x0 = (tx < 3) ? tx * 16 : 40;
            HALO_LOAD(sb + H0, n, y0, x0);
            WTAP_LOAD(sb + WT0, 0);
            CPC();
        }

        while (t2 < 896) {
            int n = t2 / 28, r = t2 - n * 28;
            int y0 = (r >> 2) * 8, tx = r & 3;
            int x0 = (tx < 3) ? tx * 16 : 40;
            uint32_t hbase = sb + (hsel ? H1 : H0);

            CPW(0);
            __syncthreads();
            if (tid == 0) s_next = atomicAdd(&g_sync[1 + parity], 1);
            __syncthreads();
            int t2n = s_next;

            int acc[2][4][4];
#pragma unroll
            for (int mt = 0; mt < 2; mt++)
#pragma unroll
                for (int nt = 0; nt < 4; nt++)
#pragma unroll
                    for (int qq = 0; qq < 4; qq++) acc[mt][nt][qq] = 0;

            for (int tap = 0; tap < 9; tap++) {
                if (tap) __syncthreads();    // previous tap done -> safe to overwrite other W buf
                if (tap < 8) {
                    WTAP_LOAD(sb + (wsel ? WT0 : WT1), tap + 1);
                    CPC();
                } else if (t2n < 896) {
                    int n2 = t2n / 28, r2 = t2n - n2 * 28;
                    while (((volatile int*)g_sync)[5 + n2] < 25) {}
                    __threadfence();
                    int y2 = (r2 >> 2) * 8, tx2 = r2 & 3;
                    int x2 = (tx2 < 3) ? tx2 * 16 : 40;
                    HALO_LOAD(sb + (hsel ? H0 : H1), n2, y2, x2);
                    WTAP_LOAD(sb + (wsel ? WT0 : WT1), 0);
                    CPC();
                }
                CPW(1);

                int dy = tap / 3, dx = tap - dy * 3;
                uint32_t wbase = sb + (wsel ? WT1 : WT0);
                uint32_t ab[2]; int axx[2];
#pragma unroll
                for (int mt = 0; mt < 2; mt++) {
                    int hrow = (yym[mt] + dy) * 18 + xxm[mt] + dx;
                    ab[mt] = hbase + hrow * 128;
                    axx[mt] = (hrow & 7) * 16;
                }
#pragma unroll
                for (int ks = 0; ks < 4; ks++) {
                    unsigned A0[4], A1[4], B[2][4];
                    ldsm4(A0, ab[0] + ((ks * 32 + kh) ^ axx[0]));
                    ldsm4(A1, ab[1] + ((ks * 32 + kh) ^ axx[1]));
#pragma unroll
                    for (int bt = 0; bt < 2; bt++)
                        ldsm4(B[bt], wbase + wof[bt] + ((ks * 32 + khb) ^ wxx[bt]));
#pragma unroll
                    for (int nt = 0; nt < 4; nt++) {
                        const unsigned* bp = &B[nt >> 1][(nt & 1) * 2];
                        mma_u8s8(acc[0][nt], A0, bp);
                        mma_u8s8(acc[1][nt], A1, bp);
                    }
                }
                wsel ^= 1;
            }

            __syncthreads();   // all taps done; reuse current halo buffer as staging
            const float* fbs = (const float*)(smem + FBo);
            char* stg = smem + (hsel ? H1 : H0);
#pragma unroll
            for (int mt = 0; mt < 2; mt++)
#pragma unroll
                for (int h = 0; h < 2; h++) {
                    int px = wrb + mt * 16 + (lane >> 2) + h * 8;
#pragma unroll
                    for (int nt = 0; nt < 4; nt++) {
                        int co = wcb + nt * 8 + (lane & 3) * 2;
                        float v0 = (float)acc[mt][nt][h * 2 + 0] * inv2 + fbs[co];
                        float v1 = (float)acc[mt][nt][h * 2 + 1] * inv2 + fbs[co + 1];
                        v0 = fminf(fmaxf(v0, 0.f), 10.f);
                        v1 = fminf(fmaxf(v1, 0.f), 10.f);
                        unsigned u0 = (unsigned)(int)rintf(v0 * 25.5f);
                        unsigned u1 = (unsigned)(int)rintf(v1 * 25.5f);
                        *(unsigned short*)(stg + px * 128 + (co ^ ((px & 7) * 16))) =
                            (unsigned short)(u0 | (u1 << 8));
                    }
                }
            __syncthreads();

            for (int u = tid; u < 512; u += 256) {
                int px = u >> 2, c16 = u & 3;
                int yy = px >> 4, xx = px & 15;
                unsigned gp = (unsigned)(n * 3136 + (y0 + yy) * 56 + (x0 + xx));
                *(uint4*)&g_act2[gp * 32 + parity * 16 + c16 * 4] =
                    *(const uint4*)(stg + px * 128 + ((c16 * 16) ^ ((px & 7) * 16)));
            }
            __threadfence();
            __syncthreads();
            if (tid == 0) atomicAdd(&g_sync[37 + n], 1);

            t2 = t2n; hsel ^= 1;
        }
    }
#undef HALO_LOAD
#undef WTAP_LOAD

    // ================= phase 3: conv3 int8 mma, co-half, 128px tiles, double-buffered act =================
    {
        __syncthreads();
        for (int u = tid; u < 2048; u += 256) {
            int row = u >> 3, c16 = u & 7;
            uint4 wv = *(const uint4*)(g_w3q + (parity * 256 + row) * 128 + c16 * 16);
            *(uint4*)(smem + SWZ(row * 128 + c16 * 16)) = wv;
        }
        if (tid < 64) ((float4*)(smem + 65536))[tid] = *(const float4*)&g_b3[parity * 256 + tid * 4];
        __syncthreads();

        const float* fb3 = (const float*)(smem + 65536);
        int sub = lane >> 3, r8 = lane & 7;
        int row8 = (sub & 1) * 8, kh = (sub >> 1) * 16;
        int cb0 = wid * 32;
        int ntl = (sub >> 1) * 8, kb = (sub & 1) * 16;

        unsigned Af[2][4][4];
#pragma unroll
        for (int amt = 0; amt < 2; amt++) {
            int co = cb0 + amt * 16 + row8 + r8;
            uint32_t base = sb + co * 128;
            int xx = (co & 7) * 16;
#pragma unroll
            for (int ks = 0; ks < 4; ks++)
                ldsm4(Af[amt][ks], base + ((ks * 32 + kh) ^ xx));
        }

        if (tid == 0) s_next = atomicAdd(&g_sync[3 + parity], 1);
        __syncthreads();
        int t3 = s_next;
        int buf3 = 0;

        if (t3 < 800) {
            int n = t3 / 25, p0 = (t3 - n * 25) * 128;
            if (tid == 0) { while (((volatile int*)g_sync)[37 + n] < 56) {} }
            __syncthreads(); __threadfence();
            for (int u = tid; u < 1024; u += 256) {
                int pix = u >> 3, c16 = u & 7;
                int p = p0 + pix;
                bool ok = p < 3136;
                const void* src = ok ? (const void*)&g_act2[((unsigned)(n * 3136 + p)) * 32 + c16 * 4]
                                     : (const void*)g_act2;
                CPA(sb + 32768 + SWZ(pix * 128 + c16 * 16), src, ok ? 16u : 0u);
            }
            CPC();
        }

        while (t3 < 800) {
            int n = t3 / 25, p0 = (t3 - n * 25) * 128;
            uint32_t aB = sb + 32768 + buf3 * 16384;

            if (tid == 0) s_next = atomicAdd(&g_sync[3 + parity], 1);
            __syncthreads();
            int t3n = s_next;
            if (t3n < 800) {
                int n2 = t3n / 25, p02 = (t3n - n2 * 25) * 128;
                if (tid == 0) { while (((volatile int*)g_sync)[37 + n2] < 56) {} }
                __syncthreads(); __threadfence();
                uint32_t dB = sb + 32768 + (buf3 ^ 1) * 16384;
                for (int u = tid; u < 1024; u += 256) {
                    int pix = u >> 3, c16 = u & 7;
                    int p = p02 + pix;
                    bool ok = p < 3136;
                    const void* src = ok ? (const void*)&g_act2[((unsigned)(n2 * 3136 + p)) * 32 + c16 * 4]
                                         : (const void*)g_act2;
                    CPA(dB + SWZ(pix * 128 + c16 * 16), src, ok ? 16u : 0u);
                }
                CPC(); CPW(1);
            } else {
                CPW(0);
            }
            __syncthreads();

            for (int pg = 0; pg < 4; pg++) {
                int acc[2][4][4];
#pragma unroll
                for (int a = 0; a < 2; a++)
#pragma unroll
                    for (int b = 0; b < 4; b++)
#pragma unroll
                        for (int qq = 0; qq < 4; qq++) acc[a][b][qq] = 0;

#pragma unroll
                for (int ks = 0; ks < 4; ks++) {
                    unsigned Bf[2][4];
#pragma unroll
                    for (int bq = 0; bq < 2; bq++) {
                        int brow = pg * 32 + bq * 16 + ntl + r8;
                        ldsm4(Bf[bq], aB + brow * 128 + (((ks * 32 + kb)) ^ ((brow & 7) * 16)));
                    }
#pragma unroll
                    for (int amt = 0; amt < 2; amt++)
#pragma unroll
                        for (int nt = 0; nt < 4; nt++)
                            mma_s8u8(acc[amt][nt], Af[amt][ks], &Bf[nt >> 1][(nt & 1) * 2]);
                }

#pragma unroll
                for (int amt = 0; amt < 2; amt++)
#pragma unroll
                    for (int h = 0; h < 2; h++) {
                        int co = parity * 256 + cb0 + amt * 16 + (lane >> 2) + h * 8;
                        float bj = fb3[co - parity * 256];
                        size_t base = ((size_t)n * 512 + co) * 3136;
#pragma unroll
                        for (int nt = 0; nt < 4; nt++) {
                            int px = p0 + pg * 32 + nt * 8 + (lane & 3) * 2;
                            if (px < 3136) {
                                float2 o2;
                                o2.x = (float)acc[amt][nt][h * 2 + 0] * inv3 + bj;
                                o2.y = (float)acc[amt][nt][h * 2 + 1] * inv3 + bj;
                                *(float2*)(out + base + px) = o2;
                            }
                        }
                    }
            }
            __syncthreads();
            t3 = t3n; buf3 ^= 1;
        }
    }
}

// ---------------- launch ----------------
extern "C" void kernel_launch(void* const* d_in, const int* in_sizes, int n_in,
                              void* d_out, int out_size)
{
    const float* x   = (const float*)d_in[0];
    const float* w1  = (const float*)d_in[1];
    const float* b1  = (const float*)d_in[2];
    const float* g1  = (const float*)d_in[3];
    const float* be1 = (const float*)d_in[4];
    const float* m1  = (const float*)d_in[5];
    const float* v1  = (const float*)d_in[6];
    const float* w2  = (const float*)d_in[7];
    const float* b2  = (const float*)d_in[8];
    const float* g2  = (const float*)d_in[9];
    const float* be2 = (const float*)d_in[10];
    const float* m2  = (const float*)d_in[11];
    const float* v2  = (const float*)d_in[12];
    const float* w3  = (const float*)d_in[13];
    const float* b3  = (const float*)d_in[14];
    const float* g3  = (const float*)d_in[15];
    const float* be3 = (const float*)d_in[16];
    const float* m3  = (const float*)d_in[17];
    const float* v3  = (const float*)d_in[18];

    cudaFuncSetAttribute(conv_fused, cudaFuncAttributeMaxDynamicSharedMemorySize, 98304);

    void* syncAddr = nullptr;
    cudaGetSymbolAddress(&syncAddr, g_sync);
    cudaMemsetAsync(syncAddr, 0, 69 * sizeof(int));
    void* maxAddr = nullptr;
    cudaGetSymbolAddress(&maxAddr, g_wmax);
    cudaMemsetAsync(maxAddr, 0, 3 * sizeof(unsigned));

    prep_max<<<96, 512>>>(w1, g1, v1, w2, g2, v2, w3, g3, v3);
    prep_quant<<<96, 512>>>(w1, b1, g1, be1, m1, v1,
                            w2, b2, g2, be2, m2, v2,
                            w3, b3, g3, be3, m3, v3);

    conv_fused<<<304, 256, 98304>>>(x, (float*)d_out);
}

// round 16
// speedup vs baseline: 1.0918x; 1.0918x over previous
#include <cuda_runtime.h>
#include <cstdint>

#define BN_EPS_F 1e-3f

__device__ __align__(16) float g_w1f[256*128];
__device__ float g_b1[128];
__device__ __align__(16) unsigned char g_w2q[9*128*128]; // [tap][co][ci] s8
__device__ float g_b2[128];
__device__ __align__(16) unsigned char g_w3q[512*128];   // [co][ci] s8
__device__ float g_b3[512];
__device__ float g_inv[2];
// [0]=c1, [1]=c2a, [2]=c2b, [3]=c3a, [4]=c3b, [5..36]=done1[n], [37..68]=done2[n], [69]=prep done
__device__ int   g_sync[70];
__device__ unsigned g_wmax[3];
__device__ __align__(16) unsigned g_act1[100352*32];
__device__ __align__(16) unsigned g_act2[100352*32];

__device__ __forceinline__ uint32_t smem_u32(const void* p){
    uint32_t a;
    asm("{ .reg .u64 t; cvta.to.shared.u64 t, %1; cvt.u32.u64 %0, t; }" : "=r"(a) : "l"(p));
    return a;
}
#define SWZ(o) ((o) ^ (((o) >> 3) & 0x70))

__device__ __forceinline__ void ldsm4(unsigned* r, uint32_t addr){
    asm volatile("ldmatrix.sync.aligned.m8n8.x4.shared.b16 {%0,%1,%2,%3}, [%4];"
        : "=r"(r[0]), "=r"(r[1]), "=r"(r[2]), "=r"(r[3]) : "r"(addr));
}
__device__ __forceinline__ void mma_u8s8(int* d, const unsigned* a, const unsigned* b){
    asm volatile("mma.sync.aligned.m16n8k32.row.col.s32.u8.s8.s32 "
        "{%0,%1,%2,%3}, {%4,%5,%6,%7}, {%8,%9}, {%0,%1,%2,%3};"
        : "+r"(d[0]), "+r"(d[1]), "+r"(d[2]), "+r"(d[3])
        : "r"(a[0]), "r"(a[1]), "r"(a[2]), "r"(a[3]), "r"(b[0]), "r"(b[1]));
}
__device__ __forceinline__ void mma_s8u8(int* d, const unsigned* a, const unsigned* b){
    asm volatile("mma.sync.aligned.m16n8k32.row.col.s32.s8.u8.s32 "
        "{%0,%1,%2,%3}, {%4,%5,%6,%7}, {%8,%9}, {%0,%1,%2,%3};"
        : "+r"(d[0]), "+r"(d[1]), "+r"(d[2]), "+r"(d[3])
        : "r"(a[0]), "r"(a[1]), "r"(a[2]), "r"(a[3]), "r"(b[0]), "r"(b[1]));
}
#define CPA(dst, src, sz) asm volatile("cp.async.cg.shared.global [%0], [%1], 16, %2;" :: "r"(dst), "l"(src), "r"(sz) : "memory")
#define CPC()  asm volatile("cp.async.commit_group;" ::: "memory")
#define CPW(n) asm volatile("cp.async.wait_group %0;" :: "n"(n) : "memory")

// ---------------- prep: max + quant in one kernel with grid-wide sync ----------------
__global__ __launch_bounds__(512) void prep_all(
    const float* __restrict__ w1, const float* __restrict__ b1,
    const float* __restrict__ g1, const float* __restrict__ be1,
    const float* __restrict__ m1, const float* __restrict__ v1,
    const float* __restrict__ w2, const float* __restrict__ b2,
    const float* __restrict__ g2, const float* __restrict__ be2,
    const float* __restrict__ m2, const float* __restrict__ v2,
    const float* __restrict__ w3, const float* __restrict__ b3,
    const float* __restrict__ g3, const float* __restrict__ be3,
    const float* __restrict__ m3, const float* __restrict__ v3)
{
    __shared__ float sc[512]; __shared__ float red[512];
    int tid = threadIdx.x;
    int grp = blockIdx.x >> 5, sub = blockIdx.x & 31;

    // ---- pass 1: per-tensor max|w*sc| ----
    float lmax = 0.f;
    if (grp == 0) {
        if (tid < 128) sc[tid] = __fdiv_rn(g1[tid], __fsqrt_rn(__fadd_rn(v1[tid], BN_EPS_F)));
        __syncthreads();
        int base = sub * 1024;
        for (int i = base + tid; i < base + 1024; i += 512)
            lmax = fmaxf(lmax, fabsf(__fmul_rn(w1[i], sc[i >> 8])));
    } else if (grp == 1) {
        if (tid < 128) sc[tid] = __fdiv_rn(g2[tid], __fsqrt_rn(__fadd_rn(v2[tid], BN_EPS_F)));
        __syncthreads();
        int base = sub * 4608;
        for (int i = base + tid; i < base + 4608; i += 512)
            lmax = fmaxf(lmax, fabsf(__fmul_rn(w2[i], sc[i / 1152])));
    } else {
        sc[tid] = __fdiv_rn(g3[tid], __fsqrt_rn(__fadd_rn(v3[tid], BN_EPS_F)));
        __syncthreads();
        int base = sub * 2048;
        for (int i = base + tid; i < base + 2048; i += 512)
            lmax = fmaxf(lmax, fabsf(__fmul_rn(w3[i], sc[i >> 7])));
    }
    red[tid] = lmax; __syncthreads();
    for (int s = 256; s > 0; s >>= 1) { if (tid < s) red[tid] = fmaxf(red[tid], red[tid+s]); __syncthreads(); }
    if (tid == 0) {
        atomicMax(&g_wmax[grp], __float_as_uint(red[0]));
        __threadfence();
        atomicAdd(&g_sync[69], 1);
        while (((volatile int*)g_sync)[69] < 96) {}
    }
    __syncthreads();
    __threadfence();

    // ---- pass 2: quantize (sc[] still valid in smem) ----
    if (grp == 0) {
        float sw = __fdiv_rn(127.f, fmaxf(__uint_as_float(g_wmax[0]), 1e-8f));
        int base = sub * 1024;
        for (int i = base + tid; i < base + 1024; i += 512) {
            float wf = __fmul_rn(w1[i], sc[i >> 8]);
            g_w1f[(i & 255) * 128 + (i >> 8)] = __fdiv_rn(rintf(__fmul_rn(wf, sw)), sw);
        }
        if (sub == 0) {
            float bf = 0.f;
            if (tid < 128) bf = __fadd_rn(__fmul_rn(__fsub_rn(b1[tid], m1[tid]), sc[tid]), be1[tid]);
            red[tid] = fabsf(bf); __syncthreads();
            for (int s = 256; s > 0; s >>= 1) { if (tid < s) red[tid] = fmaxf(red[tid], red[tid+s]); __syncthreads(); }
            float sb = __fdiv_rn(32767.f, fmaxf(red[0], 1e-8f));
            if (tid < 128) g_b1[tid] = __fdiv_rn(rintf(__fmul_rn(bf, sb)), sb);
        }
    } else if (grp == 1) {
        float sw = __fdiv_rn(127.f, fmaxf(__uint_as_float(g_wmax[1]), 1e-8f));
        int base = sub * 4608;
        for (int i = base + tid; i < base + 4608; i += 512) {
            int o = i / 1152, rem = i - o * 1152, ci = rem / 9, t = rem - ci * 9;
            int q = (int)rintf(__fmul_rn(__fmul_rn(w2[i], sc[o]), sw));
            ((signed char*)g_w2q)[(t * 128 + o) * 128 + ci] = (signed char)q;
        }
        if (sub == 0) {
            float bf = 0.f;
            if (tid < 128) bf = __fadd_rn(__fmul_rn(__fsub_rn(b2[tid], m2[tid]), sc[tid]), be2[tid]);
            red[tid] = fabsf(bf); __syncthreads();
            for (int s = 256; s > 0; s >>= 1) { if (tid < s) red[tid] = fmaxf(red[tid], red[tid+s]); __syncthreads(); }
            float sb = __fdiv_rn(32767.f, fmaxf(red[0], 1e-8f));
            if (tid < 128) g_b2[tid] = __fdiv_rn(rintf(__fmul_rn(bf, sb)), sb);
            if (tid == 0)  g_inv[0] = __fdiv_rn(1.f, __fmul_rn(sw, 25.5f));
        }
    } else {
        float sw = __fdiv_rn(127.f, fmaxf(__uint_as_float(g_wmax[2]), 1e-8f));
        int base = sub * 2048;
        for (int i = base + tid; i < base + 2048; i += 512)
            ((signed char*)g_w3q)[i] = (signed char)(int)rintf(__fmul_rn(__fmul_rn(w3[i], sc[i >> 7]), sw));
        if (sub == 0) {
            float bf = __fadd_rn(__fmul_rn(__fsub_rn(b3[tid], m3[tid]), sc[tid]), be3[tid]);
            red[tid] = fabsf(bf); __syncthreads();
            for (int s = 256; s > 0; s >>= 1) { if (tid < s) red[tid] = fmaxf(red[tid], red[tid+s]); __syncthreads(); }
            float sb = __fdiv_rn(32767.f, fmaxf(red[0], 1e-8f));
            g_b3[tid] = __fdiv_rn(rintf(__fmul_rn(bf, sb)), sb);
            if (tid == 0) g_inv[1] = __fdiv_rn(1.f, __fmul_rn(sw, 25.5f));
        }
    }
}

// ---------------- fused persistent kernel (R14 winner, verbatim) ----------------
__global__ __launch_bounds__(256, 2) void conv_fused(const float* __restrict__ x,
                                                     float* __restrict__ out)
{
    extern __shared__ char smem[];
    const uint32_t SM_W = 0, SM_H = 73728, SM_FB = 96768;
    __shared__ int s_next;
    uint32_t sb = smem_u32(smem);
    int tid = threadIdx.x, wid = tid >> 5, lane = tid & 31;
    int parity = blockIdx.x & 1;

    float inv2 = g_inv[0], inv3 = g_inv[1];

    if (tid == 0) s_next = atomicAdd(&g_sync[0], 1);
    __syncthreads();
    int t = s_next;

    // ================= phase 1: conv1 fp32, 128px x 128co =================
    {
        float* Asb = (float*)smem;
        float* Wsb = (float*)(smem + 16384);
        int tr = tid >> 4, tc = tid & 15;
        int co0 = tr * 8;
        int pxa = tc * 4, pxb = tc * 4 + 64;
        int lr = tid >> 4;
        int lc1 = (tid & 15) * 4, lc2 = lc1 + 64;

        while (t < 800) {
            int n = t / 25, p0 = (t - n * 25) * 128;
            const float* xn = x + ((size_t)n * 256) * 3136;
            int pc1 = min(p0 + lc1, 3132), pc2 = min(p0 + lc2, 3132);

            float acc[8][8];
#pragma unroll
            for (int j = 0; j < 8; j++)
#pragma unroll
                for (int q = 0; q < 8; q++) acc[j][q] = 0.f;

            float4 a1 = *(const float4*)(xn + (size_t)lr * 3136 + pc1);
            float4 a2 = *(const float4*)(xn + (size_t)lr * 3136 + pc2);
            float4 w1 = *(const float4*)(g_w1f + lr * 128 + lc1);
            float4 w2 = *(const float4*)(g_w1f + lr * 128 + lc2);
            *(float4*)(Asb + lr * 128 + lc1) = a1;
            *(float4*)(Asb + lr * 128 + lc2) = a2;
            *(float4*)(Wsb + lr * 128 + lc1) = w1;
            *(float4*)(Wsb + lr * 128 + lc2) = w2;
            __syncthreads();

            for (int p = 0; p < 16; p++) {
                int cu = (p & 1) * 2048;
                if (p < 15) {
                    int kr = (p + 1) * 16 + lr;
                    a1 = *(const float4*)(xn + (size_t)kr * 3136 + pc1);
                    a2 = *(const float4*)(xn + (size_t)kr * 3136 + pc2);
                    w1 = *(const float4*)(g_w1f + kr * 128 + lc1);
                    w2 = *(const float4*)(g_w1f + kr * 128 + lc2);
                }
#pragma unroll
                for (int k = 0; k < 16; k++) {
                    float4 av0 = *(const float4*)(Asb + cu + k * 128 + pxa);
                    float4 av1 = *(const float4*)(Asb + cu + k * 128 + pxb);
                    float4 wv0 = *(const float4*)(Wsb + cu + k * 128 + co0);
                    float4 wv1 = *(const float4*)(Wsb + cu + k * 128 + co0 + 4);
                    float wreg[8] = {wv0.x, wv0.y, wv0.z, wv0.w, wv1.x, wv1.y, wv1.z, wv1.w};
                    float areg[8] = {av0.x, av0.y, av0.z, av0.w, av1.x, av1.y, av1.z, av1.w};
#pragma unroll
                    for (int j = 0; j < 8; j++)
#pragma unroll
                        for (int q = 0; q < 8; q++)
                            acc[j][q] += wreg[j] * areg[q];
                }
                if (p < 15) {
                    int nx = ((p + 1) & 1) * 2048;
                    *(float4*)(Asb + nx + lr * 128 + lc1) = a1;
                    *(float4*)(Asb + nx + lr * 128 + lc2) = a2;
                    *(float4*)(Wsb + nx + lr * 128 + lc1) = w1;
                    *(float4*)(Wsb + nx + lr * 128 + lc2) = w2;
                    __syncthreads();
                }
            }

            float bias[8];
#pragma unroll
            for (int j = 0; j < 8; j++) bias[j] = g_b1[co0 + j];
#pragma unroll
            for (int q = 0; q < 8; q++) {
                int p = p0 + (q < 4 ? (pxa + q) : (pxb + q - 4));
                if (p >= 3136) continue;
                unsigned b0 = 0, b1v = 0;
#pragma unroll
                for (int j = 0; j < 8; j++) {
                    float vv = acc[j][q] + bias[j];
                    vv = fminf(fmaxf(vv, 0.f), 10.f);
                    unsigned a = (unsigned)(int)rintf(vv * 25.5f);
                    if (j < 4) b0 |= a << (8 * j); else b1v |= a << (8 * (j - 4));
                }
                *(uint2*)&g_act1[((unsigned)(n * 3136 + p)) * 32 + tr * 2] = make_uint2(b0, b1v);
            }
            __threadfence();
            __syncthreads();
            if (tid == 0) { atomicAdd(&g_sync[5 + n], 1); s_next = atomicAdd(&g_sync[0], 1); }
            __syncthreads();
            t = s_next;
        }
    }

    // ================= phase 2: conv2 int8 mma, co-half, resident W =================
    __syncthreads();
    for (int u = tid; u < 4608; u += 256) {
        int row = u >> 3, c16 = u & 7;
        int tp = row >> 6, c = row & 63;
        uint4 wv = *(const uint4*)(g_w2q + ((tp * 128 + parity * 64 + c) * 128) + c16 * 16);
        *(uint4*)(smem + SM_W + SWZ(row * 128 + c16 * 16)) = wv;
    }
    if (tid < 64) ((float*)(smem + SM_FB))[tid] = g_b2[parity * 64 + tid];
    __syncthreads();

    int wrb = (wid & 3) * 32, wcb = (wid >> 2) * 32;
    int sub = lane >> 3, r8 = lane & 7;
    int row8 = (sub & 1) * 8, kh = (sub >> 1) * 16;
    int rowb = (sub >> 1) * 8, khb = (sub & 1) * 16;

    int yym[2], xxm[2];
#pragma unroll
    for (int mt = 0; mt < 2; mt++) {
        int px = wrb + mt * 16 + row8 + r8;
        yym[mt] = px >> 4; xxm[mt] = px & 15;
    }
    uint32_t wbb[2]; int wxx[2];
#pragma unroll
    for (int bt = 0; bt < 2; bt++) {
        int co = wcb + bt * 16 + rowb + r8;
        wbb[bt] = sb + SM_W + co * 128;
        wxx[bt] = (co & 7) * 16;
    }

    {
        if (tid == 0) s_next = atomicAdd(&g_sync[1 + parity], 1);
        __syncthreads();
        int t2 = s_next;

        while (t2 < 896) {
            int n = t2 / 28, r = t2 - n * 28;
            int y0 = (r >> 2) * 8, tx = r & 3;
            int x0 = (tx < 3) ? tx * 16 : 40;

            if (tid == 0) { while (((volatile int*)g_sync)[5 + n] < 25) {} }
            __syncthreads(); __threadfence();

            for (int u = tid; u < 1440; u += 256) {
                int hrow = u >> 3, c16 = u & 7;
                int iy = hrow / 18, ix = hrow - iy * 18;
                int gy = y0 + iy - 1, gx = x0 + ix - 1;
                bool ok = (gy >= 0 && gy < 56 && gx >= 0 && gx < 56);
                const void* src = ok ? (const void*)&g_act1[((unsigned)(n * 3136 + gy * 56 + gx)) * 32 + c16 * 4]
                                     : (const void*)g_act1;
                CPA(sb + SM_H + SWZ(hrow * 128 + c16 * 16), src, ok ? 16u : 0u);
            }
            CPC(); CPW(0);
            __syncthreads();

            int acc[2][4][4];
#pragma unroll
            for (int mt = 0; mt < 2; mt++)
#pragma unroll
                for (int nt = 0; nt < 4; nt++)
#pragma unroll
                    for (int qq = 0; qq < 4; qq++) acc[mt][nt][qq] = 0;

            for (int dy = 0; dy < 3; dy++)
                for (int dx = 0; dx < 3; dx++) {
                    uint32_t ab[2]; int axx[2];
#pragma unroll
                    for (int mt = 0; mt < 2; mt++) {
                        int hrow = (yym[mt] + dy) * 18 + xxm[mt] + dx;
                        ab[mt] = sb + SM_H + hrow * 128;
                        axx[mt] = (hrow & 7) * 16;
                    }
                    uint32_t wtap = (dy * 3 + dx) * 8192;
#pragma unroll
                    for (int ks = 0; ks < 4; ks++) {
                        unsigned A0[4], A1[4], B[2][4];
                        ldsm4(A0, ab[0] + ((ks * 32 + kh) ^ axx[0]));
                        ldsm4(A1, ab[1] + ((ks * 32 + kh) ^ axx[1]));
#pragma unroll
                        for (int bt = 0; bt < 2; bt++)
                            ldsm4(B[bt], wbb[bt] + wtap + ((ks * 32 + khb) ^ wxx[bt]));
#pragma unroll
                        for (int nt = 0; nt < 4; nt++) {
                            const unsigned* bp = &B[nt >> 1][(nt & 1) * 2];
                            mma_u8s8(acc[0][nt], A0, bp);
                            mma_u8s8(acc[1][nt], A1, bp);
                        }
                    }
                }

            __syncthreads();
            const float* fbs = (const float*)(smem + SM_FB);
            char* stg = smem + SM_H;
#pragma unroll
            for (int mt = 0; mt < 2; mt++)
#pragma unroll
                for (int h = 0; h < 2; h++) {
                    int px = wrb + mt * 16 + (lane >> 2) + h * 8;
#pragma unroll
                    for (int nt = 0; nt < 4; nt++) {
                        int co = wcb + nt * 8 + (lane & 3) * 2;
                        float v0 = (float)acc[mt][nt][h * 2 + 0] * inv2 + fbs[co];
                        float v1 = (float)acc[mt][nt][h * 2 + 1] * inv2 + fbs[co + 1];
                        v0 = fminf(fmaxf(v0, 0.f), 10.f);
                        v1 = fminf(fmaxf(v1, 0.f), 10.f);
                        unsigned u0 = (unsigned)(int)rintf(v0 * 25.5f);
                        unsigned u1 = (unsigned)(int)rintf(v1 * 25.5f);
                        *(unsigned short*)(stg + px * 128 + (co ^ ((px & 7) * 16))) =
                            (unsigned short)(u0 | (u1 << 8));
                    }
                }
            __syncthreads();

            for (int u = tid; u < 512; u += 256) {
                int px = u >> 2, c16 = u & 3;
                int yy = px >> 4, xx = px & 15;
                unsigned gp = (unsigned)(n * 3136 + (y0 + yy) * 56 + (x0 + xx));
                *(uint4*)&g_act2[gp * 32 + parity * 16 + c16 * 4] =
                    *(const uint4*)(stg + px * 128 + ((c16 * 16) ^ ((px & 7) * 16)));
            }
            __threadfence();
            __syncthreads();
            if (tid == 0) { atomicAdd(&g_sync[37 + n], 1); s_next = atomicAdd(&g_sync[1 + parity], 1); }
            __syncthreads();
            t2 = s_next;
        }
    }

    // ================= phase 3: conv3 int8 mma, co-half, 128px tiles, double-buffered act =================
    {
        __syncthreads();
        for (int u = tid; u < 2048; u += 256) {
            int row = u >> 3, c16 = u & 7;
            uint4 wv = *(const uint4*)(g_w3q + (parity * 256 + row) * 128 + c16 * 16);
            *(uint4*)(smem + SWZ(row * 128 + c16 * 16)) = wv;
        }
        if (tid < 64) ((float4*)(smem + 65536))[tid] = *(const float4*)&g_b3[parity * 256 + tid * 4];
        __syncthreads();

        const float* fb3 = (const float*)(smem + 65536);
        int cb0 = wid * 32;
        int ntl = (sub >> 1) * 8, kb = (sub & 1) * 16;

        unsigned Af[2][4][4];
#pragma unroll
        for (int amt = 0; amt < 2; amt++) {
            int co = cb0 + amt * 16 + row8 + r8;
            uint32_t base = sb + co * 128;
            int xx = (co & 7) * 16;
#pragma unroll
            for (int ks = 0; ks < 4; ks++)
                ldsm4(Af[amt][ks], base + ((ks * 32 + kh) ^ xx));
        }

        if (tid == 0) s_next = atomicAdd(&g_sync[3 + parity], 1);
        __syncthreads();
        int t3 = s_next;
        int buf3 = 0;

        if (t3 < 800) {
            int n = t3 / 25, p0 = (t3 - n * 25) * 128;
            if (tid == 0) { while (((volatile int*)g_sync)[37 + n] < 56) {} }
            __syncthreads(); __threadfence();
            for (int u = tid; u < 1024; u += 256) {
                int pix = u >> 3, c16 = u & 7;
                int p = p0 + pix;
                bool ok = p < 3136;
                const void* src = ok ? (const void*)&g_act2[((unsigned)(n * 3136 + p)) * 32 + c16 * 4]
                                     : (const void*)g_act2;
                CPA(sb + 32768 + SWZ(pix * 128 + c16 * 16), src, ok ? 16u : 0u);
            }
            CPC();
        }

        while (t3 < 800) {
            int n = t3 / 25, p0 = (t3 - n * 25) * 128;
            uint32_t aB = sb + 32768 + buf3 * 16384;

            if (tid == 0) s_next = atomicAdd(&g_sync[3 + parity], 1);
            __syncthreads();
            int t3n = s_next;
            if (t3n < 800) {
                int n2 = t3n / 25, p02 = (t3n - n2 * 25) * 128;
                if (tid == 0) { while (((volatile int*)g_sync)[37 + n2] < 56) {} }
                __syncthreads(); __threadfence();
                uint32_t dB = sb + 32768 + (buf3 ^ 1) * 16384;
                for (int u = tid; u < 1024; u += 256) {
                    int pix = u >> 3, c16 = u & 7;
                    int p = p02 + pix;
                    bool ok = p < 3136;
                    const void* src = ok ? (const void*)&g_act2[((unsigned)(n2 * 3136 + p)) * 32 + c16 * 4]
                                         : (const void*)g_act2;
                    CPA(dB + SWZ(pix * 128 + c16 * 16), src, ok ? 16u : 0u);
                }
                CPC(); CPW(1);
            } else {
                CPW(0);
            }
            __syncthreads();

            for (int pg = 0; pg < 4; pg++) {
                int acc[2][4][4];
#pragma unroll
                for (int a = 0; a < 2; a++)
#pragma unroll
                    for (int b = 0; b < 4; b++)
#pragma unroll
                        for (int qq = 0; qq < 4; qq++) acc[a][b][qq] = 0;

#pragma unroll
                for (int ks = 0; ks < 4; ks++) {
                    unsigned Bf[2][4];
#pragma unroll
                    for (int bq = 0; bq < 2; bq++) {
                        int brow = pg * 32 + bq * 16 + ntl + r8;
                        ldsm4(Bf[bq], aB + brow * 128 + (((ks * 32 + kb)) ^ ((brow & 7) * 16)));
                    }
#pragma unroll
                    for (int amt = 0; amt < 2; amt++)
#pragma unroll
                        for (int nt = 0; nt < 4; nt++)
                            mma_s8u8(acc[amt][nt], Af[amt][ks], &Bf[nt >> 1][(nt & 1) * 2]);
                }

#pragma unroll
                for (int amt = 0; amt < 2; amt++)
#pragma unroll
                    for (int h = 0; h < 2; h++) {
                        int co = parity * 256 + cb0 + amt * 16 + (lane >> 2) + h * 8;
                        float bj = fb3[co - parity * 256];
                        size_t base = ((size_t)n * 512 + co) * 3136;
#pragma unroll
                        for (int nt = 0; nt < 4; nt++) {
                            int px = p0 + pg * 32 + nt * 8 + (lane & 3) * 2;
                            if (px < 3136) {
                                float2 o2;
                                o2.x = (float)acc[amt][nt][h * 2 + 0] * inv3 + bj;
                                o2.y = (float)acc[amt][nt][h * 2 + 1] * inv3 + bj;
                                *(float2*)(out + base + px) = o2;
                            }
                        }
                    }
            }
            __syncthreads();
            t3 = t3n; buf3 ^= 1;
        }
    }
}

// ---------------- launch ----------------
extern "C" void kernel_launch(void* const* d_in, const int* in_sizes, int n_in,
                              void* d_out, int out_size)
{
    const float* x   = (const float*)d_in[0];
    const float* w1  = (const float*)d_in[1];
    const float* b1  = (const float*)d_in[2];
    const float* g1  = (const float*)d_in[3];
    const float* be1 = (const float*)d_in[4];
    const float* m1  = (const float*)d_in[5];
    const float* v1  = (const float*)d_in[6];
    const float* w2  = (const float*)d_in[7];
    const float* b2  = (const float*)d_in[8];
    const float* g2  = (const float*)d_in[9];
    const float* be2 = (const float*)d_in[10];
    const float* m2  = (const float*)d_in[11];
    const float* v2  = (const float*)d_in[12];
    const float* w3  = (const float*)d_in[13];
    const float* b3  = (const float*)d_in[14];
    const float* g3  = (const float*)d_in[15];
    const float* be3 = (const float*)d_in[16];
    const float* m3  = (const float*)d_in[17];
    const float* v3  = (const float*)d_in[18];

    cudaFuncSetAttribute(conv_fused, cudaFuncAttributeMaxDynamicSharedMemorySize, 98304);

    void* syncAddr = nullptr;
    cudaGetSymbolAddress(&syncAddr, g_sync);
    cudaMemsetAsync(syncAddr, 0, 70 * sizeof(int));
    void* maxAddr = nullptr;
    cudaGetSymbolAddress(&maxAddr, g_wmax);
    cudaMemsetAsync(maxAddr, 0, 3 * sizeof(unsigned));

    prep_all<<<96, 512>>>(w1, b1, g1, be1, m1, v1,
                          w2, b2, g2, be2, m2, v2,
                          w3, b3, g3, be3, m3, v3);

    conv_fused<<<304, 256, 98304>>>(x, (float*)d_out);
}